// round 15
// baseline (speedup 1.0000x reference)
#include <cuda_runtime.h>
#include <math.h>

// B=1024, T=128, H1=50 (G1=200), H2=150 (G2=600), D2=100
#define B_SZ 1024
#define T_SZ 128

#define OFF_WF   0
#define OFF_PL   20480
#define OFF_FEAT 22528
#define OFF_LG   53248

typedef unsigned long long ull;
typedef unsigned int uint32;

static __device__ float  g_out1[(size_t)B_SZ * T_SZ * 100];   // layer1 output (52 MB)
static __device__ float  g_xg2 [(size_t)B_SZ * T_SZ * 600];   // layer2 fwd input proj (315 MB)
static __device__ float2 g_W2p [76 * 600];                    // layer2 fwd Whh, k-pair-major
static __device__ float  g_net [(size_t)B_SZ * 300];          // out2[:, -1]

// ---------------- fast math helpers ----------------
__device__ __forceinline__ float tanh_(float x) {
    float r; asm("tanh.approx.f32 %0, %1;" : "=f"(r) : "f"(x)); return r;
}
__device__ __forceinline__ float sigm(float x) {
    return fmaf(tanh_(0.5f * x), 0.5f, 0.5f);
}
__device__ __forceinline__ float lrelu(float x) { return x > 0.f ? x : 0.3f * x; }

__device__ __forceinline__ ull pack2(float lo, float hi) {
    ull r;
    asm("mov.b64 %0, {%1, %2};" : "=l"(r) : "r"(__float_as_uint(lo)), "r"(__float_as_uint(hi)));
    return r;
}
__device__ __forceinline__ void unpack2(ull v, float& lo, float& hi) {
    unsigned int a, b;
    asm("mov.b64 {%0, %1}, %2;" : "=r"(a), "=r"(b) : "l"(v));
    lo = __uint_as_float(a); hi = __uint_as_float(b);
}
__device__ __forceinline__ void fma2(ull& d, ull a, ull b) {
    asm("fma.rn.f32x2 %0, %1, %2, %3;" : "=l"(d) : "l"(a), "l"(b), "l"(d));
}
// pack two floats to bf16x2: LOWER 16 bits = first arg (even k), upper = second
__device__ __forceinline__ uint32 bf16pair(float lo, float hi) {
    uint32 d;
    asm("cvt.rn.satfinite.bf16x2.f32 %0, %1, %2;" : "=r"(d) : "f"(hi), "f"(lo));
    return d;
}
// HMMA m16n8k16 bf16: D += A*B (row.col), acc in-place
__device__ __forceinline__ void mma16816(float& d0, float& d1, float& d2, float& d3,
                                         uint32 a0, uint32 a1, uint32 a2, uint32 a3,
                                         uint32 b0, uint32 b1) {
    asm volatile(
        "mma.sync.aligned.m16n8k16.row.col.f32.bf16.bf16.f32 "
        "{%0,%1,%2,%3}, {%4,%5,%6,%7}, {%8,%9}, {%0,%1,%2,%3};"
        : "+f"(d0), "+f"(d1), "+f"(d2), "+f"(d3)
        : "r"(a0), "r"(a1), "r"(a2), "r"(a3), "r"(b0), "r"(b1));
}

// ---------------------------------------------------------------------------
// prep
// ---------------------------------------------------------------------------
__global__ void prep_kernel(const float* __restrict__ Whh2f)
{
    int i = blockIdx.x * 256 + threadIdx.x;
    if (i < 76 * 600) {
        int k2 = i / 600, r = i - k2 * 600;
        float lo = (2 * k2     < 150) ? Whh2f[r * 150 + 2 * k2]     : 0.f;
        float hi = (2 * k2 + 1 < 150) ? Whh2f[r * 150 + 2 * k2 + 1] : 0.f;
        g_W2p[i] = make_float2(lo, hi);
    }
}

// ---------------------------------------------------------------------------
// lstm1 (R12 proven): grid (64,2), 512 threads.
// ---------------------------------------------------------------------------
__global__ __launch_bounds__(512) void lstm1_kernel(
    const float* __restrict__ x,
    const float* __restrict__ Wih_f, const float* __restrict__ Whh_f, const float* __restrict__ b_f,
    const float* __restrict__ Wih_b, const float* __restrict__ Whh_b, const float* __restrict__ b_b)
{
    __shared__ __align__(16) float h_s[16 * 52];
    __shared__ float c_s[16 * 50];
    __shared__ float gates_s[16 * 200];
    __shared__ float x_s[16 * 128];

    const int tid = threadIdx.x;
    const int dir = blockIdx.y;
    const int b0  = blockIdx.x * 16;

    const float* Wih = dir ? Wih_b : Wih_f;
    const float* Whh = dir ? Whh_b : Whh_f;
    const float* bb  = dir ? b_b   : b_f;

    for (int i = tid; i < 16 * 128; i += 512) {
        int b = i >> 7, t = i & 127;
        x_s[i] = x[(size_t)(b0 + b) * 128 + t];
    }
    for (int i = tid; i < 16 * 52; i += 512) h_s[i] = 0.f;
    for (int i = tid; i < 16 * 50; i += 512) c_s[i] = 0.f;

    const bool comp = (tid < 400);
    const int r    = comp ? (tid % 200) : 0;
    const int bh   = comp ? (tid / 200) * 8 : 0;

    ull w2[26];
    float wih = 0.f, bv = 0.f;
    if (comp) {
#pragma unroll
        for (int k2 = 0; k2 < 26; k2++) {
            float lo = (2 * k2     < 50) ? Whh[r * 50 + 2 * k2]     : 0.f;
            float hi = (2 * k2 + 1 < 50) ? Whh[r * 50 + 2 * k2 + 1] : 0.f;
            w2[k2] = pack2(lo, hi);
        }
        wih = Wih[r];
        bv  = bb[r];
    }
    __syncthreads();

    for (int s = 0; s < T_SZ; s++) {
        const int t = dir ? (127 - s) : s;
        if (comp) {
#pragma unroll 2
            for (int bi = 0; bi < 8; bi++) {
                const int b = bh + bi;
                ull acc = pack2(fmaf(x_s[b * 128 + t], wih, bv), 0.f);
#pragma unroll
                for (int k4 = 0; k4 < 13; k4++) {
                    ulonglong2 hv = *(const ulonglong2*)(h_s + b * 52 + k4 * 4);
                    fma2(acc, hv.x, w2[2 * k4]);
                    fma2(acc, hv.y, w2[2 * k4 + 1]);
                }
                float lo, hi; unpack2(acc, lo, hi);
                gates_s[b * 200 + r] = lo + hi;
            }
        }
        __syncthreads();
        for (int p = tid; p < 16 * 50; p += 512) {
            int b = p / 50, j = p - b * 50;
            float gi = gates_s[b * 200 + j];
            float gf = gates_s[b * 200 + 50 + j];
            float gg = gates_s[b * 200 + 100 + j];
            float go = gates_s[b * 200 + 150 + j];
            float c = sigm(gf) * c_s[b * 50 + j] + sigm(gi) * tanh_(gg);
            c_s[b * 50 + j] = c;
            float h = sigm(go) * tanh_(c);
            h_s[b * 52 + j] = h;
            g_out1[(size_t)(b0 + b) * 12800 + (size_t)t * 100 + dir * 50 + j] = h;
        }
        __syncthreads();
    }
}

// ---------------------------------------------------------------------------
// xg2 via warp-level HMMA (mma.sync m16n8k16 bf16, hi/lo split -> fp32-class).
// Grid (2048, 10): CTA = 64m x 64n tile, 128 threads (4 warps, one m16 each).
// K=100 padded to 112 (7 chunks of 16). smem rows padded to 120 bf16 (240B
// stride -> conflict-free fragment loads).
// Fragment map (documented Ampere m16n8k16):
//   g=lane>>2, t=lane&3
//   a0={A[g][2t],A[g][2t+1]} a1={A[g+8][..]} a2={A[g][2t+8],..} a3={A[g+8][2t+8],..}
//   b0={B[n=g][2t],B[g][2t+1]} b1={B[g][2t+8],B[g][2t+9]}  (col-major B = k-contig per n)
//   d0=D[g][2t] d1=D[g][2t+1] d2=D[g+8][2t] d3=D[g+8][2t+1]
// smem u16: A_hi[64*120] A_lo[64*120] B_hi[64*120] B_lo[64*120] = 61440 B
// ---------------------------------------------------------------------------
#define XG2MMA_SMEM 61440

extern __shared__ uint32 xg2mma_sm[];

__global__ __launch_bounds__(128) void xg2_mma_kernel(
    const float* __restrict__ W, const float* __restrict__ bias)
{
    uint32* A_hi = xg2mma_sm;            // [row*60 + kp] (u32 = 2 bf16)
    uint32* A_lo = xg2mma_sm + 3840;
    uint32* B_hi = xg2mma_sm + 7680;     // [n*60 + kp]
    uint32* B_lo = xg2mma_sm + 11520;

    const int tid = threadIdx.x;
    const int wid = tid >> 5;
    const int lane = tid & 31;
    const int g = lane >> 2;             // group id (row / n within fragment)
    const int t = lane & 3;              // thread in group
    const int m0 = blockIdx.x * 64;
    const int n0 = blockIdx.y * 64;

    // ---- fill A (64 x 112, hi/lo) ----
    for (int i = tid; i < 3584; i += 128) {
        int row = i / 56, kp = i - row * 56;
        int k = kp * 2;
        const float* ar = g_out1 + (size_t)(m0 + row) * 100;
        float v0 = (k     < 100) ? __ldg(ar + k)     : 0.f;
        float v1 = (k + 1 < 100) ? __ldg(ar + k + 1) : 0.f;
        uint32 hp = bf16pair(v0, v1);
        float r0 = v0 - __uint_as_float((hp & 0xffffu) << 16);
        float r1 = v1 - __uint_as_float(hp & 0xffff0000u);
        A_hi[row * 60 + kp] = hp;
        A_lo[row * 60 + kp] = bf16pair(r0, r1);
    }
    // ---- fill B (64 n x 112 k, hi/lo) ----
    for (int i = tid; i < 3584; i += 128) {
        int row = i / 56, kp = i - row * 56;
        int k = kp * 2;
        int gn = n0 + row;
        float v0 = 0.f, v1 = 0.f;
        if (gn < 600) {
            const float* wr = W + gn * 100;
            v0 = (k     < 100) ? __ldg(wr + k)     : 0.f;
            v1 = (k + 1 < 100) ? __ldg(wr + k + 1) : 0.f;
        }
        uint32 hp = bf16pair(v0, v1);
        float r0 = v0 - __uint_as_float((hp & 0xffffu) << 16);
        float r1 = v1 - __uint_as_float(hp & 0xffff0000u);
        B_hi[row * 60 + kp] = hp;
        B_lo[row * 60 + kp] = bf16pair(r0, r1);
    }
    __syncthreads();

    const int nsub = (n0 + 64 <= 600) ? 8 : 3;   // last pass: n 576..599

    float acc[8][4];
#pragma unroll
    for (int s = 0; s < 8; s++)
#pragma unroll
        for (int q = 0; q < 4; q++) acc[s][q] = 0.f;

    const int arow0 = wid * 16 + g;      // A rows for this thread's fragments
    const int arow1 = arow0 + 8;

#pragma unroll
    for (int c = 0; c < 7; c++) {
        const int kh = c * 8;            // kbase/2 in u32 units
        // A fragments (hi & lo)
        uint32 ah0 = A_hi[arow0 * 60 + kh + t];
        uint32 ah1 = A_hi[arow1 * 60 + kh + t];
        uint32 ah2 = A_hi[arow0 * 60 + kh + 4 + t];
        uint32 ah3 = A_hi[arow1 * 60 + kh + 4 + t];
        uint32 al0 = A_lo[arow0 * 60 + kh + t];
        uint32 al1 = A_lo[arow1 * 60 + kh + t];
        uint32 al2 = A_lo[arow0 * 60 + kh + 4 + t];
        uint32 al3 = A_lo[arow1 * 60 + kh + 4 + t];

        for (int s = 0; s < nsub; s++) {
            const int nrow = s * 8 + g;
            uint32 bh0 = B_hi[nrow * 60 + kh + t];
            uint32 bh1 = B_hi[nrow * 60 + kh + 4 + t];
            uint32 bl0 = B_lo[nrow * 60 + kh + t];
            uint32 bl1 = B_lo[nrow * 60 + kh + 4 + t];
            mma16816(acc[s][0], acc[s][1], acc[s][2], acc[s][3],
                     ah0, ah1, ah2, ah3, bh0, bh1);
            mma16816(acc[s][0], acc[s][1], acc[s][2], acc[s][3],
                     ah0, ah1, ah2, ah3, bl0, bl1);
            mma16816(acc[s][0], acc[s][1], acc[s][2], acc[s][3],
                     al0, al1, al2, al3, bh0, bh1);
        }
    }

    // ---- store D + bias ----
    const int mg0 = m0 + wid * 16 + g;
#pragma unroll
    for (int s = 0; s < 8; s++) {
        if (s >= nsub) break;
        const int n = n0 + s * 8 + t * 2;
        if (n < 600) {
            float b0 = __ldg(bias + n);
            float b1 = __ldg(bias + n + 1);
            *(float2*)(g_xg2 + (size_t)mg0       * 600 + n) =
                make_float2(acc[s][0] + b0, acc[s][1] + b1);
            *(float2*)(g_xg2 + (size_t)(mg0 + 8) * 600 + n) =
                make_float2(acc[s][2] + b0, acc[s][3] + b1);
        }
    }
}

// ---------------------------------------------------------------------------
// lstm2 (R7 proven). 128 CTAs x 8 batches, 384 threads.
// ---------------------------------------------------------------------------
#define L2_SMEM_BYTES 206720

extern __shared__ float lstm2_sm[];

__global__ __launch_bounds__(384, 1) void lstm2_kernel()
{
    float2* Wlo  = (float2*)lstm2_sm;
    float* gates = lstm2_sm + 45600;
    float* h_s   = lstm2_sm + 45600 + 4864;

    const int tid = threadIdx.x;
    const int b0  = blockIdx.x * 8;
    const bool comp = (tid < 300);
    const int r0 = tid * 2;

    for (int i = tid; i < 11400; i += 384)
        ((float4*)lstm2_sm)[i] = ((const float4*)g_W2p)[i];
    for (int i = tid; i < 8 * 152; i += 384) h_s[i] = 0.f;

    int bs[4], js[4];
    float cs[4];
#pragma unroll
    for (int i = 0; i < 4; i++) {
        int s = tid + i * 384;
        if (s < 1200) { bs[i] = s / 150; js[i] = s - bs[i] * 150; }
        else          { bs[i] = 0;       js[i] = 0; }
        cs[i] = 0.f;
    }

    const float* xbase = g_xg2 + (size_t)b0 * 76800 + r0;

    float2 xp[8];
    if (comp) {
#pragma unroll
        for (int b = 0; b < 8; b++)
            xp[b] = *(const float2*)(xbase + (size_t)b * 76800);
    }
    __syncthreads();

    for (int t = 0; t < T_SZ; t++) {
        if (comp) {
            ull a0[8], a1[8];
#pragma unroll
            for (int b = 0; b < 8; b++) {
                a0[b] = pack2(xp[b].x, 0.f);
                a1[b] = pack2(xp[b].y, 0.f);
            }
            if (t < 127) {
#pragma unroll
                for (int b = 0; b < 8; b++)
                    xp[b] = *(const float2*)(xbase + (size_t)b * 76800 + (t + 1) * 600);
            }

            ulonglong2 wpa[4], wpb[4];
#pragma unroll
            for (int p = 0; p < 4; p++) {
                wpa[p] = __ldg((const ulonglong2*)(g_W2p + (2 * (19 + p))     * 600 + r0));
                wpb[p] = __ldg((const ulonglong2*)(g_W2p + (2 * (19 + p) + 1) * 600 + r0));
            }

#pragma unroll
            for (int it = 0; it < 19; it++) {
                ulonglong2 wA = *(const ulonglong2*)(Wlo + (2 * it)     * 600 + r0);
                ulonglong2 wB = *(const ulonglong2*)(Wlo + (2 * it + 1) * 600 + r0);
#pragma unroll
                for (int b = 0; b < 8; b++) {
                    ulonglong2 hv = *(const ulonglong2*)(h_s + b * 152 + it * 4);
                    fma2(a0[b], hv.x, wA.x);
                    fma2(a0[b], hv.y, wB.x);
                    fma2(a1[b], hv.x, wA.y);
                    fma2(a1[b], hv.y, wB.y);
                }
            }
#pragma unroll
            for (int it = 19; it < 38; it++) {
                const int slot = (it - 19) & 3;
                ulonglong2 wA = wpa[slot];
                ulonglong2 wB = wpb[slot];
                if (it + 4 < 38) {
                    wpa[slot] = __ldg((const ulonglong2*)(g_W2p + (2 * (it + 4))     * 600 + r0));
                    wpb[slot] = __ldg((const ulonglong2*)(g_W2p + (2 * (it + 4) + 1) * 600 + r0));
                }
#pragma unroll
                for (int b = 0; b < 8; b++) {
                    ulonglong2 hv = *(const ulonglong2*)(h_s + b * 152 + it * 4);
                    fma2(a0[b], hv.x, wA.x);
                    fma2(a0[b], hv.y, wB.x);
                    fma2(a1[b], hv.x, wA.y);
                    fma2(a1[b], hv.y, wB.y);
                }
            }

#pragma unroll
            for (int b = 0; b < 8; b++) {
                float l0, h0, l1, h1;
                unpack2(a0[b], l0, h0);
                unpack2(a1[b], l1, h1);
                *(float2*)(gates + b * 608 + r0) = make_float2(l0 + h0, l1 + h1);
            }
        }
        __syncthreads();

#pragma unroll
        for (int i = 0; i < 4; i++) {
            int s = tid + i * 384;
            if (s < 1200) {
                int b = bs[i], j = js[i];
                float gi = gates[b * 608 + j];
                float gf = gates[b * 608 + 150 + j];
                float gg = gates[b * 608 + 300 + j];
                float go = gates[b * 608 + 450 + j];
                float c = sigm(gf) * cs[i] + sigm(gi) * tanh_(gg);
                cs[i] = c;
                float h = sigm(go) * tanh_(c);
                h_s[b * 152 + j] = h;
                if (t == 127) g_net[(size_t)(b0 + b) * 300 + j] = h;
            }
        }
        __syncthreads();
    }
}

// ---------------------------------------------------------------------------
// bwd2
// ---------------------------------------------------------------------------
__global__ __launch_bounds__(256) void bwd2_kernel(
    const float* __restrict__ Wih2b, const float* __restrict__ b2b)
{
    __shared__ float xv[4 * 100];
    __shared__ float gsm[4 * 600];
    const int tid = threadIdx.x;
    const int b0  = blockIdx.x * 4;

    for (int i = tid; i < 400; i += 256) {
        int b = i / 100, c = i - b * 100;
        xv[i] = g_out1[(size_t)(b0 + b) * 12800 + 127 * 100 + c];
    }
    __syncthreads();

    for (int p = tid; p < 2400; p += 256) {
        int b = p / 600, rr = p - b * 600;
        float acc = b2b[rr];
        const float* Wr = Wih2b + rr * 100;
        const float* xr = xv + b * 100;
#pragma unroll 4
        for (int k = 0; k < 100; k++) acc = fmaf(Wr[k], xr[k], acc);
        gsm[b * 600 + rr] = acc;
    }
    __syncthreads();

    for (int p = tid; p < 600; p += 256) {
        int b = p / 150, j = p - b * 150;
        float gi = gsm[b * 600 + j];
        float gg = gsm[b * 600 + 300 + j];
        float go = gsm[b * 600 + 450 + j];
        float c = sigm(gi) * tanh_(gg);
        float h = sigm(go) * tanh_(c);
        g_net[(size_t)(b0 + b) * 300 + 150 + j] = h;
    }
}

// ---------------------------------------------------------------------------
// heads
// ---------------------------------------------------------------------------
__global__ __launch_bounds__(32) void heads_kernel(
    const float* __restrict__ rrs,
    const float* __restrict__ head_W, const float* __restrict__ head_b,
    const float* __restrict__ pef1_W, const float* __restrict__ pef1_b,
    const float* __restrict__ pef2_W, const float* __restrict__ pef2_b,
    const float* __restrict__ fc_W,   const float* __restrict__ fc_b,
    float* __restrict__ out)
{
    __shared__ float net_s[300];
    __shared__ float feat_s[30];
    __shared__ float rrs_s[4];
    const int b = blockIdx.x;
    const int tid = threadIdx.x;

    for (int i = tid; i < 300; i += 32) net_s[i] = g_net[(size_t)b * 300 + i];
    if (tid < 4) rrs_s[tid] = rrs[b * 4 + tid];
    __syncthreads();

    if (tid < 20) {
        float acc = head_b[tid];
        const float* Wr = head_W + tid * 300;
        for (int k = 0; k < 300; k++) acc = fmaf(Wr[k], net_s[k], acc);
        float v = lrelu(acc);
        feat_s[tid] = v;
        out[OFF_WF + b * 20 + tid] = v;
    } else if (tid < 30) {
        int j = tid - 20;
        float acc = pef1_b[j];
#pragma unroll
        for (int k = 0; k < 4; k++) acc = fmaf(pef1_W[j * 4 + k], rrs_s[k], acc);
        feat_s[20 + j] = lrelu(acc);
    }
    __syncthreads();

    if (tid < 2) {
        float acc = pef2_b[tid];
#pragma unroll
        for (int k = 0; k < 10; k++) acc = fmaf(pef2_W[tid * 10 + k], feat_s[20 + k], acc);
        out[OFF_PL + b * 2 + tid] = acc;
    } else if (tid < 6) {
        int j = tid - 2;
        float acc = fc_b[j];
#pragma unroll
        for (int k = 0; k < 30; k++) acc = fmaf(fc_W[j * 30 + k], feat_s[k], acc);
        out[OFF_LG + b * 4 + j] = acc;
    }
    if (tid < 30) out[OFF_FEAT + b * 30 + tid] = feat_s[tid];
}

// ---------------------------------------------------------------------------
extern "C" void kernel_launch(void* const* d_in, const int* in_sizes, int n_in,
                              void* d_out, int out_size)
{
    const float* x        = (const float*)d_in[0];
    const float* rrs      = (const float*)d_in[1];
    const float* l1_Wih_f = (const float*)d_in[2];
    const float* l1_Whh_f = (const float*)d_in[3];
    const float* l1_b_f   = (const float*)d_in[4];
    const float* l1_Wih_b = (const float*)d_in[5];
    const float* l1_Whh_b = (const float*)d_in[6];
    const float* l1_b_b   = (const float*)d_in[7];
    const float* l2_Wih_f = (const float*)d_in[8];
    const float* l2_Whh_f = (const float*)d_in[9];
    const float* l2_b_f   = (const float*)d_in[10];
    const float* l2_Wih_b = (const float*)d_in[11];
    /* d_in[12] = l2_Whh_b unused (single backward step from h0=0) */
    const float* l2_b_b   = (const float*)d_in[13];
    const float* head_W   = (const float*)d_in[14];
    const float* head_b   = (const float*)d_in[15];
    const float* pef1_W   = (const float*)d_in[16];
    const float* pef1_b   = (const float*)d_in[17];
    const float* pef2_W   = (const float*)d_in[18];
    const float* pef2_b   = (const float*)d_in[19];
    const float* fc_W     = (const float*)d_in[20];
    const float* fc_b     = (const float*)d_in[21];
    float* out = (float*)d_out;

    (void)cudaFuncSetAttribute(lstm2_kernel,
                               cudaFuncAttributeMaxDynamicSharedMemorySize, L2_SMEM_BYTES);
    (void)cudaFuncSetAttribute(xg2_mma_kernel,
                               cudaFuncAttributeMaxDynamicSharedMemorySize, XG2MMA_SMEM);

    prep_kernel<<<(76 * 600 + 255) / 256, 256>>>(l2_Whh_f);
    lstm1_kernel<<<dim3(64, 2), 512>>>(x, l1_Wih_f, l1_Whh_f, l1_b_f,
                                          l1_Wih_b, l1_Whh_b, l1_b_b);
    xg2_mma_kernel<<<dim3(2048, 10), 128, XG2MMA_SMEM>>>(l2_Wih_f, l2_b_f);
    lstm2_kernel<<<128, 384, L2_SMEM_BYTES>>>();
    bwd2_kernel<<<256, 256>>>(l2_Wih_b, l2_b_b);
    heads_kernel<<<1024, 32>>>(rrs, head_W, head_b, pef1_W, pef1_b,
                               pef2_W, pef2_b, fc_W, fc_b, out);
}

// round 16
// speedup vs baseline: 1.1951x; 1.1951x over previous
#include <cuda_runtime.h>
#include <math.h>

// B=1024, T=128, H1=50 (G1=200), H2=150 (G2=600), D2=100
#define B_SZ 1024
#define T_SZ 128

#define OFF_WF   0
#define OFF_PL   20480
#define OFF_FEAT 22528
#define OFF_LG   53248

typedef unsigned long long ull;
typedef unsigned int uint32;

static __device__ float  g_out1[(size_t)B_SZ * T_SZ * 100];   // layer1 output (52 MB)
static __device__ float  g_xg2 [(size_t)B_SZ * T_SZ * 600];   // layer2 fwd input proj (315 MB)
static __device__ float2 g_W2p [76 * 600];                    // layer2 fwd Whh, k-pair-major
static __device__ float  g_net [(size_t)B_SZ * 300];          // out2[:, -1]
static __device__ uint32 g_Ahi[(size_t)131072 * 56];          // out1 bf16-hi k-pairs (29 MB)
static __device__ uint32 g_Alo[(size_t)131072 * 56];          // out1 bf16-lo k-pairs (29 MB)
static __device__ uint32 g_Bhi[600 * 56];                     // Wih2f bf16-hi k-pairs
static __device__ uint32 g_Blo[600 * 56];                     // Wih2f bf16-lo k-pairs

// ---------------- fast math helpers ----------------
__device__ __forceinline__ float tanh_(float x) {
    float r; asm("tanh.approx.f32 %0, %1;" : "=f"(r) : "f"(x)); return r;
}
__device__ __forceinline__ float sigm(float x) {
    return fmaf(tanh_(0.5f * x), 0.5f, 0.5f);
}
__device__ __forceinline__ float lrelu(float x) { return x > 0.f ? x : 0.3f * x; }

__device__ __forceinline__ ull pack2(float lo, float hi) {
    ull r;
    asm("mov.b64 %0, {%1, %2};" : "=l"(r) : "r"(__float_as_uint(lo)), "r"(__float_as_uint(hi)));
    return r;
}
__device__ __forceinline__ void unpack2(ull v, float& lo, float& hi) {
    unsigned int a, b;
    asm("mov.b64 {%0, %1}, %2;" : "=r"(a), "=r"(b) : "l"(v));
    lo = __uint_as_float(a); hi = __uint_as_float(b);
}
__device__ __forceinline__ void fma2(ull& d, ull a, ull b) {
    asm("fma.rn.f32x2 %0, %1, %2, %3;" : "=l"(d) : "l"(a), "l"(b), "l"(d));
}
// pack two floats to bf16x2: LOWER 16 bits = first arg (even k), upper = second
__device__ __forceinline__ uint32 bf16pair(float lo, float hi) {
    uint32 d;
    asm("cvt.rn.satfinite.bf16x2.f32 %0, %1, %2;" : "=r"(d) : "f"(hi), "f"(lo));
    return d;
}
// HMMA m16n8k16 bf16: D += A*B (row.col), acc in-place
__device__ __forceinline__ void mma16816(float& d0, float& d1, float& d2, float& d3,
                                         uint32 a0, uint32 a1, uint32 a2, uint32 a3,
                                         uint32 b0, uint32 b1) {
    asm volatile(
        "mma.sync.aligned.m16n8k16.row.col.f32.bf16.bf16.f32 "
        "{%0,%1,%2,%3}, {%4,%5,%6,%7}, {%8,%9}, {%0,%1,%2,%3};"
        : "+f"(d0), "+f"(d1), "+f"(d2), "+f"(d3)
        : "r"(a0), "r"(a1), "r"(a2), "r"(a3), "r"(b0), "r"(b1));
}
// split one float pair into bf16 hi/lo pairs
__device__ __forceinline__ void hilo(float v0, float v1, uint32& hp, uint32& lp) {
    hp = bf16pair(v0, v1);
    float r0 = v0 - __uint_as_float((hp & 0xffffu) << 16);
    float r1 = v1 - __uint_as_float(hp & 0xffff0000u);
    lp = bf16pair(r0, r1);
}

// ---------------------------------------------------------------------------
// prep: Whh2f k-pair transpose (for lstm2)
// ---------------------------------------------------------------------------
__global__ void prep_kernel(const float* __restrict__ Whh2f)
{
    int i = blockIdx.x * 256 + threadIdx.x;
    if (i < 76 * 600) {
        int k2 = i / 600, r = i - k2 * 600;
        float lo = (2 * k2     < 150) ? Whh2f[r * 150 + 2 * k2]     : 0.f;
        float hi = (2 * k2 + 1 < 150) ? Whh2f[r * 150 + 2 * k2 + 1] : 0.f;
        g_W2p[i] = make_float2(lo, hi);
    }
}

// bconv: Wih2f (600x100) -> g_Bhi/g_Blo [600][56] (K padded to 112)
__global__ void bconv_kernel(const float* __restrict__ W)
{
    int i = blockIdx.x * 256 + threadIdx.x;
    if (i < 600 * 56) {
        int n = i / 56, kp = i - n * 56;
        int k = kp * 2;
        float v0 = (k     < 100) ? W[n * 100 + k]     : 0.f;
        float v1 = (k + 1 < 100) ? W[n * 100 + k + 1] : 0.f;
        uint32 hp, lp; hilo(v0, v1, hp, lp);
        g_Bhi[i] = hp; g_Blo[i] = lp;
    }
}

// aconv: g_out1 (131072x100) -> g_Ahi/g_Alo [m][56]
__global__ __launch_bounds__(256) void aconv_kernel()
{
    int i = blockIdx.x * 256 + threadIdx.x;   // exactly 131072*56 = 28672*256
    int m = i / 56, kp = i - m * 56;
    int k = kp * 2;
    const float* ar = g_out1 + (size_t)m * 100;
    float v0 = (k     < 100) ? __ldg(ar + k)     : 0.f;
    float v1 = (k + 1 < 100) ? __ldg(ar + k + 1) : 0.f;
    uint32 hp, lp; hilo(v0, v1, hp, lp);
    g_Ahi[i] = hp; g_Alo[i] = lp;
}

// ---------------------------------------------------------------------------
// lstm1 (R12 proven): grid (64,2), 512 threads.
// ---------------------------------------------------------------------------
__global__ __launch_bounds__(512) void lstm1_kernel(
    const float* __restrict__ x,
    const float* __restrict__ Wih_f, const float* __restrict__ Whh_f, const float* __restrict__ b_f,
    const float* __restrict__ Wih_b, const float* __restrict__ Whh_b, const float* __restrict__ b_b)
{
    __shared__ __align__(16) float h_s[16 * 52];
    __shared__ float c_s[16 * 50];
    __shared__ float gates_s[16 * 200];
    __shared__ float x_s[16 * 128];

    const int tid = threadIdx.x;
    const int dir = blockIdx.y;
    const int b0  = blockIdx.x * 16;

    const float* Wih = dir ? Wih_b : Wih_f;
    const float* Whh = dir ? Whh_b : Whh_f;
    const float* bb  = dir ? b_b   : b_f;

    for (int i = tid; i < 16 * 128; i += 512) {
        int b = i >> 7, t = i & 127;
        x_s[i] = x[(size_t)(b0 + b) * 128 + t];
    }
    for (int i = tid; i < 16 * 52; i += 512) h_s[i] = 0.f;
    for (int i = tid; i < 16 * 50; i += 512) c_s[i] = 0.f;

    const bool comp = (tid < 400);
    const int r    = comp ? (tid % 200) : 0;
    const int bh   = comp ? (tid / 200) * 8 : 0;

    ull w2[26];
    float wih = 0.f, bv = 0.f;
    if (comp) {
#pragma unroll
        for (int k2 = 0; k2 < 26; k2++) {
            float lo = (2 * k2     < 50) ? Whh[r * 50 + 2 * k2]     : 0.f;
            float hi = (2 * k2 + 1 < 50) ? Whh[r * 50 + 2 * k2 + 1] : 0.f;
            w2[k2] = pack2(lo, hi);
        }
        wih = Wih[r];
        bv  = bb[r];
    }
    __syncthreads();

    for (int s = 0; s < T_SZ; s++) {
        const int t = dir ? (127 - s) : s;
        if (comp) {
#pragma unroll 2
            for (int bi = 0; bi < 8; bi++) {
                const int b = bh + bi;
                ull acc = pack2(fmaf(x_s[b * 128 + t], wih, bv), 0.f);
#pragma unroll
                for (int k4 = 0; k4 < 13; k4++) {
                    ulonglong2 hv = *(const ulonglong2*)(h_s + b * 52 + k4 * 4);
                    fma2(acc, hv.x, w2[2 * k4]);
                    fma2(acc, hv.y, w2[2 * k4 + 1]);
                }
                float lo, hi; unpack2(acc, lo, hi);
                gates_s[b * 200 + r] = lo + hi;
            }
        }
        __syncthreads();
        for (int p = tid; p < 16 * 50; p += 512) {
            int b = p / 50, j = p - b * 50;
            float gi = gates_s[b * 200 + j];
            float gf = gates_s[b * 200 + 50 + j];
            float gg = gates_s[b * 200 + 100 + j];
            float go = gates_s[b * 200 + 150 + j];
            float c = sigm(gf) * c_s[b * 50 + j] + sigm(gi) * tanh_(gg);
            c_s[b * 50 + j] = c;
            float h = sigm(go) * tanh_(c);
            h_s[b * 52 + j] = h;
            g_out1[(size_t)(b0 + b) * 12800 + (size_t)t * 100 + dir * 50 + j] = h;
        }
        __syncthreads();
    }
}

// ---------------------------------------------------------------------------
// xg2 v2 via HMMA with precomputed bf16 hi/lo operands.
// Grid 1024 CTAs x 256 threads (8 warps, m16 each -> 128 rows/CTA).
// A fragments register-resident (7 k-chunks); loop 75 n8-tiles, B from L2.
// Fragment map validated in R15 (rel_err 3.5e-6).
// ---------------------------------------------------------------------------
__global__ __launch_bounds__(256) void xg2_mma2_kernel(const float* __restrict__ bias)
{
    __shared__ float bias_s[600];
    const int tid = threadIdx.x;
    const int wid = tid >> 5;
    const int lane = tid & 31;
    const int g = lane >> 2;
    const int t = lane & 3;
    const int mb = blockIdx.x * 128 + wid * 16;

    for (int i = tid; i < 600; i += 256) bias_s[i] = bias[i];
    __syncthreads();

    const uint32* Ah0 = g_Ahi + (size_t)(mb + g)     * 56;
    const uint32* Ah1 = g_Ahi + (size_t)(mb + 8 + g) * 56;
    const uint32* Al0 = g_Alo + (size_t)(mb + g)     * 56;
    const uint32* Al1 = g_Alo + (size_t)(mb + 8 + g) * 56;

    uint32 ah[7][4], al[7][4];
#pragma unroll
    for (int c = 0; c < 7; c++) {
        ah[c][0] = __ldg(Ah0 + c * 8 + t);
        ah[c][1] = __ldg(Ah1 + c * 8 + t);
        ah[c][2] = __ldg(Ah0 + c * 8 + 4 + t);
        ah[c][3] = __ldg(Ah1 + c * 8 + 4 + t);
        al[c][0] = __ldg(Al0 + c * 8 + t);
        al[c][1] = __ldg(Al1 + c * 8 + t);
        al[c][2] = __ldg(Al0 + c * 8 + 4 + t);
        al[c][3] = __ldg(Al1 + c * 8 + 4 + t);
    }

    for (int s = 0; s < 75; s++) {
        float d0 = 0.f, d1 = 0.f, d2 = 0.f, d3 = 0.f;
        const uint32* Bh = g_Bhi + (s * 8 + g) * 56;
        const uint32* Bl = g_Blo + (s * 8 + g) * 56;
#pragma unroll
        for (int c = 0; c < 7; c++) {
            uint32 bh0 = __ldg(Bh + c * 8 + t);
            uint32 bh1 = __ldg(Bh + c * 8 + 4 + t);
            uint32 bl0 = __ldg(Bl + c * 8 + t);
            uint32 bl1 = __ldg(Bl + c * 8 + 4 + t);
            mma16816(d0, d1, d2, d3, ah[c][0], ah[c][1], ah[c][2], ah[c][3], bh0, bh1);
            mma16816(d0, d1, d2, d3, ah[c][0], ah[c][1], ah[c][2], ah[c][3], bl0, bl1);
            mma16816(d0, d1, d2, d3, al[c][0], al[c][1], al[c][2], al[c][3], bh0, bh1);
        }
        const int n = s * 8 + t * 2;     // 600 = 75*8, no tail
        float b0 = bias_s[n], b1 = bias_s[n + 1];
        *(float2*)(g_xg2 + (size_t)(mb + g)     * 600 + n) = make_float2(d0 + b0, d1 + b1);
        *(float2*)(g_xg2 + (size_t)(mb + 8 + g) * 600 + n) = make_float2(d2 + b0, d3 + b1);
    }
}

// ---------------------------------------------------------------------------
// lstm2 (R7 proven). 128 CTAs x 8 batches, 384 threads.
// ---------------------------------------------------------------------------
#define L2_SMEM_BYTES 206720

extern __shared__ float lstm2_sm[];

__global__ __launch_bounds__(384, 1) void lstm2_kernel()
{
    float2* Wlo  = (float2*)lstm2_sm;
    float* gates = lstm2_sm + 45600;
    float* h_s   = lstm2_sm + 45600 + 4864;

    const int tid = threadIdx.x;
    const int b0  = blockIdx.x * 8;
    const bool comp = (tid < 300);
    const int r0 = tid * 2;

    for (int i = tid; i < 11400; i += 384)
        ((float4*)lstm2_sm)[i] = ((const float4*)g_W2p)[i];
    for (int i = tid; i < 8 * 152; i += 384) h_s[i] = 0.f;

    int bs[4], js[4];
    float cs[4];
#pragma unroll
    for (int i = 0; i < 4; i++) {
        int s = tid + i * 384;
        if (s < 1200) { bs[i] = s / 150; js[i] = s - bs[i] * 150; }
        else          { bs[i] = 0;       js[i] = 0; }
        cs[i] = 0.f;
    }

    const float* xbase = g_xg2 + (size_t)b0 * 76800 + r0;

    float2 xp[8];
    if (comp) {
#pragma unroll
        for (int b = 0; b < 8; b++)
            xp[b] = *(const float2*)(xbase + (size_t)b * 76800);
    }
    __syncthreads();

    for (int t = 0; t < T_SZ; t++) {
        if (comp) {
            ull a0[8], a1[8];
#pragma unroll
            for (int b = 0; b < 8; b++) {
                a0[b] = pack2(xp[b].x, 0.f);
                a1[b] = pack2(xp[b].y, 0.f);
            }
            if (t < 127) {
#pragma unroll
                for (int b = 0; b < 8; b++)
                    xp[b] = *(const float2*)(xbase + (size_t)b * 76800 + (t + 1) * 600);
            }

            ulonglong2 wpa[4], wpb[4];
#pragma unroll
            for (int p = 0; p < 4; p++) {
                wpa[p] = __ldg((const ulonglong2*)(g_W2p + (2 * (19 + p))     * 600 + r0));
                wpb[p] = __ldg((const ulonglong2*)(g_W2p + (2 * (19 + p) + 1) * 600 + r0));
            }

#pragma unroll
            for (int it = 0; it < 19; it++) {
                ulonglong2 wA = *(const ulonglong2*)(Wlo + (2 * it)     * 600 + r0);
                ulonglong2 wB = *(const ulonglong2*)(Wlo + (2 * it + 1) * 600 + r0);
#pragma unroll
                for (int b = 0; b < 8; b++) {
                    ulonglong2 hv = *(const ulonglong2*)(h_s + b * 152 + it * 4);
                    fma2(a0[b], hv.x, wA.x);
                    fma2(a0[b], hv.y, wB.x);
                    fma2(a1[b], hv.x, wA.y);
                    fma2(a1[b], hv.y, wB.y);
                }
            }
#pragma unroll
            for (int it = 19; it < 38; it++) {
                const int slot = (it - 19) & 3;
                ulonglong2 wA = wpa[slot];
                ulonglong2 wB = wpb[slot];
                if (it + 4 < 38) {
                    wpa[slot] = __ldg((const ulonglong2*)(g_W2p + (2 * (it + 4))     * 600 + r0));
                    wpb[slot] = __ldg((const ulonglong2*)(g_W2p + (2 * (it + 4) + 1) * 600 + r0));
                }
#pragma unroll
                for (int b = 0; b < 8; b++) {
                    ulonglong2 hv = *(const ulonglong2*)(h_s + b * 152 + it * 4);
                    fma2(a0[b], hv.x, wA.x);
                    fma2(a0[b], hv.y, wB.x);
                    fma2(a1[b], hv.x, wA.y);
                    fma2(a1[b], hv.y, wB.y);
                }
            }

#pragma unroll
            for (int b = 0; b < 8; b++) {
                float l0, h0, l1, h1;
                unpack2(a0[b], l0, h0);
                unpack2(a1[b], l1, h1);
                *(float2*)(gates + b * 608 + r0) = make_float2(l0 + h0, l1 + h1);
            }
        }
        __syncthreads();

#pragma unroll
        for (int i = 0; i < 4; i++) {
            int s = tid + i * 384;
            if (s < 1200) {
                int b = bs[i], j = js[i];
                float gi = gates[b * 608 + j];
                float gf = gates[b * 608 + 150 + j];
                float gg = gates[b * 608 + 300 + j];
                float go = gates[b * 608 + 450 + j];
                float c = sigm(gf) * cs[i] + sigm(gi) * tanh_(gg);
                cs[i] = c;
                float h = sigm(go) * tanh_(c);
                h_s[b * 152 + j] = h;
                if (t == 127) g_net[(size_t)(b0 + b) * 300 + j] = h;
            }
        }
        __syncthreads();
    }
}

// ---------------------------------------------------------------------------
// bwd2
// ---------------------------------------------------------------------------
__global__ __launch_bounds__(256) void bwd2_kernel(
    const float* __restrict__ Wih2b, const float* __restrict__ b2b)
{
    __shared__ float xv[4 * 100];
    __shared__ float gsm[4 * 600];
    const int tid = threadIdx.x;
    const int b0  = blockIdx.x * 4;

    for (int i = tid; i < 400; i += 256) {
        int b = i / 100, c = i - b * 100;
        xv[i] = g_out1[(size_t)(b0 + b) * 12800 + 127 * 100 + c];
    }
    __syncthreads();

    for (int p = tid; p < 2400; p += 256) {
        int b = p / 600, rr = p - b * 600;
        float acc = b2b[rr];
        const float* Wr = Wih2b + rr * 100;
        const float* xr = xv + b * 100;
#pragma unroll 4
        for (int k = 0; k < 100; k++) acc = fmaf(Wr[k], xr[k], acc);
        gsm[b * 600 + rr] = acc;
    }
    __syncthreads();

    for (int p = tid; p < 600; p += 256) {
        int b = p / 150, j = p - b * 150;
        float gi = gsm[b * 600 + j];
        float gg = gsm[b * 600 + 300 + j];
        float go = gsm[b * 600 + 450 + j];
        float c = sigm(gi) * tanh_(gg);
        float h = sigm(go) * tanh_(c);
        g_net[(size_t)(b0 + b) * 300 + 150 + j] = h;
    }
}

// ---------------------------------------------------------------------------
// heads
// ---------------------------------------------------------------------------
__global__ __launch_bounds__(32) void heads_kernel(
    const float* __restrict__ rrs,
    const float* __restrict__ head_W, const float* __restrict__ head_b,
    const float* __restrict__ pef1_W, const float* __restrict__ pef1_b,
    const float* __restrict__ pef2_W, const float* __restrict__ pef2_b,
    const float* __restrict__ fc_W,   const float* __restrict__ fc_b,
    float* __restrict__ out)
{
    __shared__ float net_s[300];
    __shared__ float feat_s[30];
    __shared__ float rrs_s[4];
    const int b = blockIdx.x;
    const int tid = threadIdx.x;

    for (int i = tid; i < 300; i += 32) net_s[i] = g_net[(size_t)b * 300 + i];
    if (tid < 4) rrs_s[tid] = rrs[b * 4 + tid];
    __syncthreads();

    if (tid < 20) {
        float acc = head_b[tid];
        const float* Wr = head_W + tid * 300;
        for (int k = 0; k < 300; k++) acc = fmaf(Wr[k], net_s[k], acc);
        float v = lrelu(acc);
        feat_s[tid] = v;
        out[OFF_WF + b * 20 + tid] = v;
    } else if (tid < 30) {
        int j = tid - 20;
        float acc = pef1_b[j];
#pragma unroll
        for (int k = 0; k < 4; k++) acc = fmaf(pef1_W[j * 4 + k], rrs_s[k], acc);
        feat_s[20 + j] = lrelu(acc);
    }
    __syncthreads();

    if (tid < 2) {
        float acc = pef2_b[tid];
#pragma unroll
        for (int k = 0; k < 10; k++) acc = fmaf(pef2_W[tid * 10 + k], feat_s[20 + k], acc);
        out[OFF_PL + b * 2 + tid] = acc;
    } else if (tid < 6) {
        int j = tid - 2;
        float acc = fc_b[j];
#pragma unroll
        for (int k = 0; k < 30; k++) acc = fmaf(fc_W[j * 30 + k], feat_s[k], acc);
        out[OFF_LG + b * 4 + j] = acc;
    }
    if (tid < 30) out[OFF_FEAT + b * 30 + tid] = feat_s[tid];
}

// ---------------------------------------------------------------------------
extern "C" void kernel_launch(void* const* d_in, const int* in_sizes, int n_in,
                              void* d_out, int out_size)
{
    const float* x        = (const float*)d_in[0];
    const float* rrs      = (const float*)d_in[1];
    const float* l1_Wih_f = (const float*)d_in[2];
    const float* l1_Whh_f = (const float*)d_in[3];
    const float* l1_b_f   = (const float*)d_in[4];
    const float* l1_Wih_b = (const float*)d_in[5];
    const float* l1_Whh_b = (const float*)d_in[6];
    const float* l1_b_b   = (const float*)d_in[7];
    const float* l2_Wih_f = (const float*)d_in[8];
    const float* l2_Whh_f = (const float*)d_in[9];
    const float* l2_b_f   = (const float*)d_in[10];
    const float* l2_Wih_b = (const float*)d_in[11];
    /* d_in[12] = l2_Whh_b unused (single backward step from h0=0) */
    const float* l2_b_b   = (const float*)d_in[13];
    const float* head_W   = (const float*)d_in[14];
    const float* head_b   = (const float*)d_in[15];
    const float* pef1_W   = (const float*)d_in[16];
    const float* pef1_b   = (const float*)d_in[17];
    const float* pef2_W   = (const float*)d_in[18];
    const float* pef2_b   = (const float*)d_in[19];
    const float* fc_W     = (const float*)d_in[20];
    const float* fc_b     = (const float*)d_in[21];
    float* out = (float*)d_out;

    (void)cudaFuncSetAttribute(lstm2_kernel,
                               cudaFuncAttributeMaxDynamicSharedMemorySize, L2_SMEM_BYTES);

    prep_kernel<<<(76 * 600 + 255) / 256, 256>>>(l2_Whh_f);
    bconv_kernel<<<(600 * 56 + 255) / 256, 256>>>(l2_Wih_f);
    lstm1_kernel<<<dim3(64, 2), 512>>>(x, l1_Wih_f, l1_Whh_f, l1_b_f,
                                          l1_Wih_b, l1_Whh_b, l1_b_b);
    aconv_kernel<<<28672, 256>>>();
    xg2_mma2_kernel<<<1024, 256>>>(l2_b_f);
    lstm2_kernel<<<128, 384, L2_SMEM_BYTES>>>();
    bwd2_kernel<<<256, 256>>>(l2_Wih_b, l2_b_b);
    heads_kernel<<<1024, 32>>>(rrs, head_W, head_b, pef1_W, pef1_b,
                               pef2_W, pef2_b, fc_W, fc_b, out);
}